// round 4
// baseline (speedup 1.0000x reference)
#include <cuda_runtime.h>
#include <cuda_bf16.h>

// RMSNorm over last axis: x[4, 8192, 2048] fp32, weight[2048] fp32.
// out = x * rsqrt(mean(x^2) + 1e-6) * weight
//
// R2 design (3rd submission; two broker-side container failures, which occur
// before kernel compile and are uncorrelated with source): warp-per-row.
// Each warp loads an entire 8KB row (16 x LDG.128 per lane), butterfly-reduces
// sum-of-squares with NO block barriers, then streams out. Streaming cache
// hints (ldcs/stcs) since x/out have zero reuse.
// Goal: lift DRAM% from 77 -> 85+ by removing block-barrier serialization.

#define NCOLS 2048
#define THREADS 256
#define WARPS_PER_BLOCK (THREADS / 32)          // 8 rows per block
#define VECS_PER_ROW (NCOLS / 4)                // 512 float4 per row
#define VECS_PER_LANE (VECS_PER_ROW / 32)       // 16 float4 per lane
#define EPSF 1e-6f

__global__ __launch_bounds__(THREADS, 2)
void rmsnorm_warprow_kernel(const float4* __restrict__ x4,
                            const float4* __restrict__ w4,
                            float4* __restrict__ out4)
{
    const int warp = threadIdx.x >> 5;
    const int lane = threadIdx.x & 31;
    const long long row = (long long)blockIdx.x * WARPS_PER_BLOCK + warp;

    const float4* xr = x4 + row * VECS_PER_ROW;
    float4* outr = out4 + row * VECS_PER_ROW;

    // Front-batched row load: 16 independent LDG.128 per lane (warp covers
    // 512B contiguous per step -> perfectly coalesced). Evict-first: no reuse.
    float4 v[VECS_PER_LANE];
    #pragma unroll
    for (int i = 0; i < VECS_PER_LANE; i++)
        v[i] = __ldcs(xr + i * 32 + lane);

    // Sum of squares
    float ss = 0.0f;
    #pragma unroll
    for (int i = 0; i < VECS_PER_LANE; i++) {
        ss = fmaf(v[i].x, v[i].x, ss);
        ss = fmaf(v[i].y, v[i].y, ss);
        ss = fmaf(v[i].z, v[i].z, ss);
        ss = fmaf(v[i].w, v[i].w, ss);
    }

    // Warp butterfly reduce — all lanes end with the full row sum.
    #pragma unroll
    for (int off = 16; off > 0; off >>= 1)
        ss += __shfl_xor_sync(0xFFFFFFFFu, ss, off);

    const float inv_rms = rsqrtf(ss * (1.0f / (float)NCOLS) + EPSF);

    // Scale by weight (L1/L2-resident, 8KB) and stream out.
    #pragma unroll
    for (int i = 0; i < VECS_PER_LANE; i++) {
        const float4 wv = __ldg(w4 + i * 32 + lane);
        float4 o;
        o.x = v[i].x * inv_rms * wv.x;
        o.y = v[i].y * inv_rms * wv.y;
        o.z = v[i].z * inv_rms * wv.z;
        o.w = v[i].w * inv_rms * wv.w;
        __stcs(outr + i * 32 + lane, o);
    }
}

extern "C" void kernel_launch(void* const* d_in, const int* in_sizes, int n_in,
                              void* d_out, int out_size)
{
    const float4* x4 = (const float4*)d_in[0];   // [4, 8192, 2048]
    const float4* w4 = (const float4*)d_in[1];   // [2048]
    float4* out4 = (float4*)d_out;

    const int nrows = in_sizes[0] / NCOLS;       // 32768
    const int nblocks = nrows / WARPS_PER_BLOCK; // 4096
    rmsnorm_warprow_kernel<<<nblocks, THREADS>>>(x4, w4, out4);
}